// round 9
// baseline (speedup 1.0000x reference)
#include <cuda_runtime.h>
#include <cstdint>

// Problem constants
#define PB  4
#define PS  2048
#define PD  1024
#define PH  16
#define PDH 64
#define MROWS (PB*PS)        // 8192
#define O_ELEMS (MROWS*PD)   // 8388608  (offset of attn in d_out)

// ---------------- device scratch (static: no allocations allowed) -------------
__device__ float g_qh[(size_t)PB*PH*PS*PDH]; // [B,H,S,dh]
__device__ float g_kh[(size_t)PB*PH*PS*PDH]; // [B,H,S,dh]
__device__ float g_vt[(size_t)PB*PH*PDH*PS]; // [B,H,dh,S]  (transposed V)
__device__ float g_os[(size_t)PB*PS*PD];     // merged attention output [B,S,D]

// ---------------- tf32 helpers ------------------------------------------------
__device__ __forceinline__ uint32_t f2tf(float x) {
    uint32_t u; asm("cvt.rna.tf32.f32 %0, %1;" : "=r"(u) : "f"(x)); return u;
}
__device__ __forceinline__ void mma8(float* d, const uint32_t* a, const uint32_t* b) {
    asm volatile(
        "mma.sync.aligned.m16n8k8.row.col.f32.tf32.tf32.f32 "
        "{%0,%1,%2,%3},{%4,%5,%6,%7},{%8,%9},{%0,%1,%2,%3};"
        : "+f"(d[0]), "+f"(d[1]), "+f"(d[2]), "+f"(d[3])
        : "r"(a[0]), "r"(a[1]), "r"(a[2]), "r"(a[3]), "r"(b[0]), "r"(b[1]));
}

// ---------------- projection GEMM (double-buffered) --------------------------
// C[M,N] = X[M,K] @ W[N,K]^T. BM=128, BN=64, BK=32, 256 thr, warps 4x2 (32x32).
// LAYOUT 0: scatter [B,H,S,dh] | 1: scatter [B,H,dh,S] | 2: flat + residual
template<int LAYOUT>
__global__ __launch_bounds__(256, 2)
void proj_kernel(const float* __restrict__ X, const float* __restrict__ W,
                 const float* __restrict__ RES, float* __restrict__ OUT)
{
    extern __shared__ uint32_t psm[];
    uint32_t* As = psm;                 // 2 buffers of 128*36
    uint32_t* Bs = psm + 2 * 128 * 36;  // 2 buffers of 64*36
    const int tid = threadIdx.x;
    const int m0 = blockIdx.y * 128;
    const int n0 = blockIdx.x * 64;
    const int warpId = tid >> 5, lane = tid & 31;
    const int g = lane >> 2, t = lane & 3;
    const int wm = warpId >> 1, wn = warpId & 1;
    const int rowBase = wm * 32, colBase = wn * 32;

    float4 ra[4], rb[2];
    auto loadRegs = [&](int kt) {
#pragma unroll
        for (int i = 0; i < 4; i++) {
            int q4 = tid + i * 256, r = q4 >> 3, c4 = q4 & 7;
            ra[i] = *(const float4*)(X + (size_t)(m0 + r) * PD + kt + c4 * 4);
        }
#pragma unroll
        for (int i = 0; i < 2; i++) {
            int q4 = tid + i * 256, r = q4 >> 3, c4 = q4 & 7;
            rb[i] = *(const float4*)(W + (size_t)(n0 + r) * PD + kt + c4 * 4);
        }
    };
    auto storeRegs = [&](int buf) {
        uint32_t* Ad = As + buf * (128 * 36);
        uint32_t* Bd = Bs + buf * (64 * 36);
#pragma unroll
        for (int i = 0; i < 4; i++) {
            int q4 = tid + i * 256, r = q4 >> 3, c4 = q4 & 7;
            int o = r * 36 + c4 * 4;
            Ad[o + 0] = f2tf(ra[i].x); Ad[o + 1] = f2tf(ra[i].y);
            Ad[o + 2] = f2tf(ra[i].z); Ad[o + 3] = f2tf(ra[i].w);
        }
#pragma unroll
        for (int i = 0; i < 2; i++) {
            int q4 = tid + i * 256, r = q4 >> 3, c4 = q4 & 7;
            int o = r * 36 + c4 * 4;
            Bd[o + 0] = f2tf(rb[i].x); Bd[o + 1] = f2tf(rb[i].y);
            Bd[o + 2] = f2tf(rb[i].z); Bd[o + 3] = f2tf(rb[i].w);
        }
    };

    float acc[2][4][4];
#pragma unroll
    for (int i = 0; i < 2; i++)
#pragma unroll
        for (int j = 0; j < 4; j++)
#pragma unroll
            for (int r = 0; r < 4; r++) acc[i][j][r] = 0.f;

    loadRegs(0); storeRegs(0); __syncthreads();

    for (int it = 0; it < 32; it++) {
        int cur = it & 1;
        if (it < 31) loadRegs((it + 1) * 32);
        const uint32_t* Ac = As + cur * (128 * 36);
        const uint32_t* Bc = Bs + cur * (64 * 36);
#pragma unroll
        for (int kk = 0; kk < 32; kk += 8) {
            uint32_t af[2][4], bf[4][2];
#pragma unroll
            for (int mi = 0; mi < 2; mi++) {
                int r = rowBase + mi * 16;
                af[mi][0] = Ac[(r + g) * 36 + kk + t];
                af[mi][1] = Ac[(r + g + 8) * 36 + kk + t];
                af[mi][2] = Ac[(r + g) * 36 + kk + t + 4];
                af[mi][3] = Ac[(r + g + 8) * 36 + kk + t + 4];
            }
#pragma unroll
            for (int ni = 0; ni < 4; ni++) {
                int c = colBase + ni * 8;
                bf[ni][0] = Bc[(c + g) * 36 + kk + t];
                bf[ni][1] = Bc[(c + g) * 36 + kk + t + 4];
            }
#pragma unroll
            for (int mi = 0; mi < 2; mi++)
#pragma unroll
                for (int ni = 0; ni < 4; ni++)
                    mma8(acc[mi][ni], af[mi], bf[ni]);
        }
        if (it < 31) storeRegs(cur ^ 1);
        __syncthreads();
    }

    // epilogue
#pragma unroll
    for (int mi = 0; mi < 2; mi++)
#pragma unroll
        for (int ni = 0; ni < 4; ni++)
#pragma unroll
            for (int h2 = 0; h2 < 2; h2++) {
                int row = m0 + rowBase + mi * 16 + g + h2 * 8;
                int col = n0 + colBase + ni * 8 + 2 * t;
                float v0 = acc[mi][ni][h2 * 2 + 0];
                float v1 = acc[mi][ni][h2 * 2 + 1];
                if (LAYOUT == 0) {
                    int b = row >> 11, s = row & (PS - 1);
                    int hh = col >> 6, d = col & 63;
                    size_t idx = ((size_t)(b * PH + hh) * PS + s) * PDH + d;
                    OUT[idx] = v0; OUT[idx + 1] = v1;
                } else if (LAYOUT == 1) {
                    int b = row >> 11, s = row & (PS - 1);
                    int hh = col >> 6, d = col & 63;
                    size_t idx = ((size_t)(b * PH + hh) * PDH + d) * PS + s;
                    OUT[idx] = v0; OUT[idx + PS] = v1;
                } else {
                    size_t idx = (size_t)row * PD + col;
                    OUT[idx]     = v0 + RES[idx];
                    OUT[idx + 1] = v1 + RES[idx + 1];
                }
            }
}

// ---------------- fused attention (512 threads, 16 warps) --------------------
// Block = (bh, qt): 128 query rows of one head.
// Warp grid 4x4: S warp tile 32x32, O warp tile 32x16.
// Pass 1: stream K (double-buffered), online per-row stats (4 stripes/row).
// Pass 2: re-stream K (L2-hot), recompute S bitwise-identically, p=exp(s-m)*inv,
//         write attn, stage tf32 P, accumulate P@V.
__global__ __launch_bounds__(512, 1)
void fused_attn_kernel(const float* __restrict__ QH, const float* __restrict__ KH,
                       const float* __restrict__ VT,
                       float* __restrict__ ATTN, float* __restrict__ OS)
{
    extern __shared__ uint32_t sm[];
    uint32_t* Qs = sm;                       // 128*68          = 8704
    uint32_t* Kb = sm + 8704;                // 2 * 128*68      = 17408
    uint32_t* Vb = sm + 26112;               // 64*132          = 8448
    uint32_t* Ps = sm + 34560;               // 128*132         = 16896
    float* sM   = (float*)(sm + 51456);      // 4*128
    float* sS   = sM + 512;                  // 4*128
    float* rowM = sS + 512;                  // 128
    float* rowI = rowM + 128;                // 128   (end: 52736 u32)

    const int tid = threadIdx.x;
    const int qt = blockIdx.x, bh = blockIdx.y;
    const int warpId = tid >> 5, lane = tid & 31;
    const int g = lane >> 2, t = lane & 3;
    const int wm = warpId >> 2, wn = warpId & 3;   // 4x4 warp grid
    const int rowBase = wm * 32;
    const int colS = wn * 32;                      // S-col stripe

    const float* qbase = QH + ((size_t)bh * PS + qt * 128) * PDH;
    const float* kbase = KH + (size_t)bh * PS * PDH;
    const float* vbase = VT + (size_t)bh * PDH * PS;
    float* outbase = ATTN + ((size_t)bh * PS + qt * 128) * PS;

    // load Q tile once (tf32): 2048 float4, 4 per thread
#pragma unroll
    for (int i = 0; i < 4; i++) {
        int q4 = tid + i * 512, r = q4 >> 4, c4 = q4 & 15;
        float4 v = *(const float4*)(qbase + (size_t)r * PDH + c4 * 4);
        int o = r * 68 + c4 * 4;
        Qs[o + 0] = f2tf(v.x); Qs[o + 1] = f2tf(v.y);
        Qs[o + 2] = f2tf(v.z); Qs[o + 3] = f2tf(v.w);
    }

    float mrun[4], srun[4];
#pragma unroll
    for (int i = 0; i < 4; i++) { mrun[i] = -1e30f; srun[i] = 0.f; }

    float acc[2][4][4];

    // ---------------- pass 1: stats only ----------------
    {
        float4 kr[4];
        auto loadK = [&](int kt) {
            const float* kb = kbase + (size_t)kt * 128 * PDH;
#pragma unroll
            for (int i = 0; i < 4; i++) {
                int q4 = tid + i * 512, r = q4 >> 4, c4 = q4 & 15;
                kr[i] = *(const float4*)(kb + (size_t)r * PDH + c4 * 4);
            }
        };
        auto storeK = [&](int buf) {
            uint32_t* kd = Kb + buf * 8704;
#pragma unroll
            for (int i = 0; i < 4; i++) {
                int q4 = tid + i * 512, r = q4 >> 4, c4 = q4 & 15;
                int o = r * 68 + c4 * 4;
                kd[o + 0] = f2tf(kr[i].x); kd[o + 1] = f2tf(kr[i].y);
                kd[o + 2] = f2tf(kr[i].z); kd[o + 3] = f2tf(kr[i].w);
            }
        };

        loadK(0); storeK(0);
        __syncthreads();

        for (int kt = 0; kt < 16; kt++) {
            int cur = kt & 1;
            if (kt < 15) loadK(kt + 1);
            const uint32_t* kd = Kb + cur * 8704;
#pragma unroll
            for (int i = 0; i < 2; i++)
#pragma unroll
                for (int j = 0; j < 4; j++)
#pragma unroll
                    for (int r = 0; r < 4; r++) acc[i][j][r] = 0.f;
#pragma unroll
            for (int kk = 0; kk < 64; kk += 8) {
                uint32_t af[2][4], bf[4][2];
#pragma unroll
                for (int mi = 0; mi < 2; mi++) {
                    int r = rowBase + mi * 16;
                    af[mi][0] = Qs[(r + g) * 68 + kk + t];
                    af[mi][1] = Qs[(r + g + 8) * 68 + kk + t];
                    af[mi][2] = Qs[(r + g) * 68 + kk + t + 4];
                    af[mi][3] = Qs[(r + g + 8) * 68 + kk + t + 4];
                }
#pragma unroll
                for (int ni = 0; ni < 4; ni++) {
                    int c = colS + ni * 8;
                    bf[ni][0] = kd[(c + g) * 68 + kk + t];
                    bf[ni][1] = kd[(c + g) * 68 + kk + t + 4];
                }
#pragma unroll
                for (int mi = 0; mi < 2; mi++)
#pragma unroll
                    for (int ni = 0; ni < 4; ni++)
                        mma8(acc[mi][ni], af[mi], bf[ni]);
            }
            // online stats over this tile (per 32-col warp stripe)
#pragma unroll
            for (int mi = 0; mi < 2; mi++)
#pragma unroll
                for (int h2 = 0; h2 < 2; h2++) {
                    int idx = mi * 2 + h2;
                    float vmax = -1e30f;
#pragma unroll
                    for (int ni = 0; ni < 4; ni++) {
                        vmax = fmaxf(vmax, acc[mi][ni][h2 * 2 + 0]);
                        vmax = fmaxf(vmax, acc[mi][ni][h2 * 2 + 1]);
                    }
                    vmax = fmaxf(vmax, __shfl_xor_sync(0xffffffffu, vmax, 1));
                    vmax = fmaxf(vmax, __shfl_xor_sync(0xffffffffu, vmax, 2));
                    float mn = fmaxf(mrun[idx], vmax * 0.125f);
                    float ps = 0.f;
#pragma unroll
                    for (int ni = 0; ni < 4; ni++) {
                        ps += __expf(acc[mi][ni][h2 * 2 + 0] * 0.125f - mn);
                        ps += __expf(acc[mi][ni][h2 * 2 + 1] * 0.125f - mn);
                    }
                    ps += __shfl_xor_sync(0xffffffffu, ps, 1);
                    ps += __shfl_xor_sync(0xffffffffu, ps, 2);
                    srun[idx] = srun[idx] * __expf(mrun[idx] - mn) + ps;
                    mrun[idx] = mn;
                }
            if (kt < 15) storeK(cur ^ 1);
            __syncthreads();
        }
    }

    // merge the four 32-col stripes per row
    if ((lane & 3) == 0) {
#pragma unroll
        for (int mi = 0; mi < 2; mi++)
#pragma unroll
            for (int h2 = 0; h2 < 2; h2++) {
                int row = rowBase + mi * 16 + h2 * 8 + g;
                sM[wn * 128 + row] = mrun[mi * 2 + h2];
                sS[wn * 128 + row] = srun[mi * 2 + h2];
            }
    }
    __syncthreads();
    if (tid < 128) {
        float m0 = sM[tid],       m1 = sM[128 + tid];
        float m2 = sM[256 + tid], m3 = sM[384 + tid];
        float m = fmaxf(fmaxf(m0, m1), fmaxf(m2, m3));
        float s = sS[tid] * __expf(m0 - m) + sS[128 + tid] * __expf(m1 - m)
                + sS[256 + tid] * __expf(m2 - m) + sS[384 + tid] * __expf(m3 - m);
        rowM[tid] = m; rowI[tid] = 1.0f / s;
    }
    __syncthreads();

    float rm[4], ri[4];
#pragma unroll
    for (int mi = 0; mi < 2; mi++)
#pragma unroll
        for (int h2 = 0; h2 < 2; h2++) {
            int row = rowBase + mi * 16 + h2 * 8 + g;
            rm[mi * 2 + h2] = rowM[row];
            ri[mi * 2 + h2] = rowI[row];
        }

    float oacc[2][2][4];
#pragma unroll
    for (int i = 0; i < 2; i++)
#pragma unroll
        for (int j = 0; j < 2; j++)
#pragma unroll
            for (int r = 0; r < 4; r++) oacc[i][j][r] = 0.f;

    const int colO = wn * 16;   // O-col stripe (128x64 O, 4 col-warps x 16)

    // ---------------- pass 2: recompute S -> p -> attn write + P@V ----------
    for (int kt = 0; kt < 16; kt++) {
        // load K tile (buffer 0) + V tile
        {
            const float* kb = kbase + (size_t)kt * 128 * PDH;
#pragma unroll
            for (int i = 0; i < 4; i++) {
                int q4 = tid + i * 512, r = q4 >> 4, c4 = q4 & 15;
                float4 v = *(const float4*)(kb + (size_t)r * PDH + c4 * 4);
                int o = r * 68 + c4 * 4;
                Kb[o + 0] = f2tf(v.x); Kb[o + 1] = f2tf(v.y);
                Kb[o + 2] = f2tf(v.z); Kb[o + 3] = f2tf(v.w);
            }
#pragma unroll
            for (int i = 0; i < 4; i++) {
                int q4 = tid + i * 512, d = q4 >> 5, c4 = q4 & 31;
                float4 v = *(const float4*)(vbase + (size_t)d * PS + kt * 128 + c4 * 4);
                int o = d * 132 + c4 * 4;
                Vb[o + 0] = f2tf(v.x); Vb[o + 1] = f2tf(v.y);
                Vb[o + 2] = f2tf(v.z); Vb[o + 3] = f2tf(v.w);
            }
        }
        __syncthreads();

        // recompute S (identical math to pass 1)
#pragma unroll
        for (int i = 0; i < 2; i++)
#pragma unroll
            for (int j = 0; j < 4; j++)
#pragma unroll
                for (int r = 0; r < 4; r++) acc[i][j][r] = 0.f;
#pragma unroll
        for (int kk = 0; kk < 64; kk += 8) {
            uint32_t af[2][4], bf[4][2];
#pragma unroll
            for (int mi = 0; mi < 2; mi++) {
                int r = rowBase + mi * 16;
                af[mi][0] = Qs[(r + g) * 68 + kk + t];
                af[mi][1] = Qs[(r + g + 8) * 68 + kk + t];
                af[mi][2] = Qs[(r + g) * 68 + kk + t + 4];
                af[mi][3] = Qs[(r + g + 8) * 68 + kk + t + 4];
            }
#pragma unroll
            for (int ni = 0; ni < 4; ni++) {
                int c = colS + ni * 8;
                bf[ni][0] = Kb[(c + g) * 68 + kk + t];
                bf[ni][1] = Kb[(c + g) * 68 + kk + t + 4];
            }
#pragma unroll
            for (int mi = 0; mi < 2; mi++)
#pragma unroll
                for (int ni = 0; ni < 4; ni++)
                    mma8(acc[mi][ni], af[mi], bf[ni]);
        }

        // p = exp(s - m) * inv ; write attn; stage tf32 P
#pragma unroll
        for (int mi = 0; mi < 2; mi++)
#pragma unroll
            for (int ni = 0; ni < 4; ni++)
#pragma unroll
                for (int h2 = 0; h2 < 2; h2++) {
                    int idx = mi * 2 + h2;
                    int row = rowBase + mi * 16 + h2 * 8 + g;
                    int cl = colS + ni * 8 + 2 * t;
                    float p0 = __expf(acc[mi][ni][h2 * 2 + 0] * 0.125f - rm[idx]) * ri[idx];
                    float p1 = __expf(acc[mi][ni][h2 * 2 + 1] * 0.125f - rm[idx]) * ri[idx];
                    float2 st; st.x = p0; st.y = p1;
                    *(float2*)(outbase + (size_t)row * PS + kt * 128 + cl) = st;
                    Ps[row * 132 + cl]     = f2tf(p0);
                    Ps[row * 132 + cl + 1] = f2tf(p1);
                }
        __syncthreads();

        // P @ V  (warp tile 32x16 over O[128x64])
#pragma unroll
        for (int kk = 0; kk < 128; kk += 8) {
            uint32_t afv[2][4], bfv[2][2];
#pragma unroll
            for (int mi = 0; mi < 2; mi++) {
                int r = rowBase + mi * 16;
                afv[mi][0] = Ps[(r + g) * 132 + kk + t];
                afv[mi][1] = Ps[(r + g + 8) * 132 + kk + t];
                afv[mi][2] = Ps[(r + g) * 132 + kk + t + 4];
                afv[mi][3] = Ps[(r + g + 8) * 132 + kk + t + 4];
            }
#pragma unroll
            for (int ni = 0; ni < 2; ni++) {
                int c = colO + ni * 8;
                bfv[ni][0] = Vb[(c + g) * 132 + kk + t];
                bfv[ni][1] = Vb[(c + g) * 132 + kk + t + 4];
            }
#pragma unroll
            for (int mi = 0; mi < 2; mi++)
#pragma unroll
                for (int ni = 0; ni < 2; ni++)
                    mma8(oacc[mi][ni], afv[mi], bfv[ni]);
        }
        __syncthreads();
    }

    // O epilogue -> merged [B,S,D]
    int b = bh >> 4, hh = bh & 15;
#pragma unroll
    for (int mi = 0; mi < 2; mi++)
#pragma unroll
        for (int ni = 0; ni < 2; ni++)
#pragma unroll
            for (int h2 = 0; h2 < 2; h2++) {
                int row = rowBase + mi * 16 + h2 * 8 + g;
                int col = colO + ni * 8 + 2 * t;
                size_t idx = (size_t)(b * PS + qt * 128 + row) * PD + hh * 64 + col;
                float2 st;
                st.x = oacc[mi][ni][h2 * 2 + 0];
                st.y = oacc[mi][ni][h2 * 2 + 1];
                *(float2*)(OS + idx) = st;
            }
}

// ---------------- in-place LayerNorm over rows of d_out ----------------------
__global__ __launch_bounds__(256)
void ln_kernel(float* __restrict__ OUT, const float* __restrict__ LW,
               const float* __restrict__ LB)
{
    __shared__ float red[16];
    const int row = blockIdx.x, tid = threadIdx.x;
    float* rp = OUT + (size_t)row * PD;
    float4 v = *(const float4*)(rp + tid * 4);
    float s1 = v.x + v.y + v.z + v.w;
    float s2 = v.x * v.x + v.y * v.y + v.z * v.z + v.w * v.w;
#pragma unroll
    for (int o = 16; o; o >>= 1) {
        s1 += __shfl_xor_sync(0xffffffffu, s1, o);
        s2 += __shfl_xor_sync(0xffffffffu, s2, o);
    }
    int w = tid >> 5, l = tid & 31;
    if (l == 0) { red[w] = s1; red[w + 8] = s2; }
    __syncthreads();
    if (w == 0) {
        float a  = (l < 8) ? red[l] : 0.f;
        float b2 = (l < 8) ? red[l + 8] : 0.f;
#pragma unroll
        for (int o = 4; o; o >>= 1) {
            a  += __shfl_xor_sync(0xffffffffu, a, o);
            b2 += __shfl_xor_sync(0xffffffffu, b2, o);
        }
        if (l == 0) { red[0] = a; red[1] = b2; }
    }
    __syncthreads();
    float mean = red[0] * (1.0f / PD);
    float var  = red[1] * (1.0f / PD) - mean * mean;
    float inv  = rsqrtf(var + 1e-6f);
    float4 w4 = *(const float4*)(LW + tid * 4);
    float4 b4 = *(const float4*)(LB + tid * 4);
    float4 o4;
    o4.x = (v.x - mean) * inv * w4.x + b4.x;
    o4.y = (v.y - mean) * inv * w4.y + b4.y;
    o4.z = (v.z - mean) * inv * w4.z + b4.z;
    o4.w = (v.w - mean) * inv * w4.w + b4.w;
    *(float4*)(rp + tid * 4) = o4;
}

// ---------------- launcher ---------------------------------------------------
extern "C" void kernel_launch(void* const* d_in, const int* in_sizes, int n_in,
                              void* d_out, int out_size)
{
    const float* q   = (const float*)d_in[0];
    const float* k   = (const float*)d_in[1];
    const float* v   = (const float*)d_in[2];
    const float* wq  = (const float*)d_in[3];
    const float* wk  = (const float*)d_in[4];
    const float* wv  = (const float*)d_in[5];
    const float* wfc = (const float*)d_in[6];
    const float* lnw = (const float*)d_in[7];
    const float* lnb = (const float*)d_in[8];
    float* out  = (float*)d_out;
    float* attn = out + (size_t)O_ELEMS;   // outputs concatenated: o then attn

    float *qh, *kh, *vt, *os;
    cudaGetSymbolAddress((void**)&qh, g_qh);
    cudaGetSymbolAddress((void**)&kh, g_kh);
    cudaGetSymbolAddress((void**)&vt, g_vt);
    cudaGetSymbolAddress((void**)&os, g_os);

    const int proj_smem  = (2 * 128 * 36 + 2 * 64 * 36) * 4;   // 55296 B
    const int fused_smem = 52736 * 4;                          // 210944 B
    cudaFuncSetAttribute(proj_kernel<0>,
                         cudaFuncAttributeMaxDynamicSharedMemorySize, proj_smem);
    cudaFuncSetAttribute(proj_kernel<1>,
                         cudaFuncAttributeMaxDynamicSharedMemorySize, proj_smem);
    cudaFuncSetAttribute(proj_kernel<2>,
                         cudaFuncAttributeMaxDynamicSharedMemorySize, proj_smem);
    cudaFuncSetAttribute(fused_attn_kernel,
                         cudaFuncAttributeMaxDynamicSharedMemorySize, fused_smem);

    proj_kernel<0><<<dim3(16, 64), 256, proj_smem>>>(q, wq, nullptr, qh);
    proj_kernel<0><<<dim3(16, 64), 256, proj_smem>>>(k, wk, nullptr, kh);
    proj_kernel<1><<<dim3(16, 64), 256, proj_smem>>>(v, wv, nullptr, vt);
    fused_attn_kernel<<<dim3(16, 64), 512, fused_smem>>>(qh, kh, vt, attn, os);
    proj_kernel<2><<<dim3(16, 64), 256, proj_smem>>>(os, wfc, q, out);
    ln_kernel<<<MROWS, 256>>>(out, lnw, lnb);
}

// round 10
// speedup vs baseline: 1.0608x; 1.0608x over previous
#include <cuda_runtime.h>
#include <cstdint>

// Problem constants
#define PB  4
#define PS  2048
#define PD  1024
#define PH  16
#define PDH 64
#define MROWS (PB*PS)        // 8192
#define O_ELEMS (MROWS*PD)   // 8388608  (offset of attn in d_out)

// ---------------- device scratch (static: no allocations allowed) -------------
__device__ float g_qh[(size_t)PB*PH*PS*PDH]; // [B,H,S,dh]
__device__ float g_kh[(size_t)PB*PH*PS*PDH]; // [B,H,S,dh]
__device__ float g_vt[(size_t)PB*PH*PDH*PS]; // [B,H,dh,S]  (transposed V)
__device__ float g_os[(size_t)PB*PS*PD];     // merged attention output [B,S,D]

// ---------------- tf32 helpers ------------------------------------------------
__device__ __forceinline__ uint32_t f2tf(float x) {
    uint32_t u; asm("cvt.rna.tf32.f32 %0, %1;" : "=r"(u) : "f"(x)); return u;
}
__device__ __forceinline__ void mma8(float* d, const uint32_t* a, const uint32_t* b) {
    asm volatile(
        "mma.sync.aligned.m16n8k8.row.col.f32.tf32.tf32.f32 "
        "{%0,%1,%2,%3},{%4,%5,%6,%7},{%8,%9},{%0,%1,%2,%3};"
        : "+f"(d[0]), "+f"(d[1]), "+f"(d[2]), "+f"(d[3])
        : "r"(a[0]), "r"(a[1]), "r"(a[2]), "r"(a[3]), "r"(b[0]), "r"(b[1]));
}

// ---------------- projection GEMM (double-buffered, BN=128) ------------------
// C[M,N] = X[M,K] @ W[N,K]^T. BM=128, BN=128, BK=32, 256 thr, warps 4x2,
// warp tile 32x64 (better LDS:MMA ratio than 32x32).
// LAYOUT 0: scatter [B,H,S,dh] | 1: scatter [B,H,dh,S] | 2: flat + residual
template<int LAYOUT>
__global__ __launch_bounds__(256)
void proj_kernel(const float* __restrict__ X, const float* __restrict__ W,
                 const float* __restrict__ RES, float* __restrict__ OUT)
{
    extern __shared__ uint32_t psm[];
    uint32_t* As = psm;                 // 2 buffers of 128*36
    uint32_t* Bs = psm + 2 * 128 * 36;  // 2 buffers of 128*36
    const int tid = threadIdx.x;
    const int m0 = blockIdx.y * 128;
    const int n0 = blockIdx.x * 128;
    const int warpId = tid >> 5, lane = tid & 31;
    const int g = lane >> 2, t = lane & 3;
    const int wm = warpId >> 1, wn = warpId & 1;
    const int rowBase = wm * 32, colBase = wn * 64;

    float4 ra[4], rb[4];
    auto loadRegs = [&](int kt) {
#pragma unroll
        for (int i = 0; i < 4; i++) {
            int q4 = tid + i * 256, r = q4 >> 3, c4 = q4 & 7;
            ra[i] = *(const float4*)(X + (size_t)(m0 + r) * PD + kt + c4 * 4);
            rb[i] = *(const float4*)(W + (size_t)(n0 + r) * PD + kt + c4 * 4);
        }
    };
    auto storeRegs = [&](int buf) {
        uint32_t* Ad = As + buf * (128 * 36);
        uint32_t* Bd = Bs + buf * (128 * 36);
#pragma unroll
        for (int i = 0; i < 4; i++) {
            int q4 = tid + i * 256, r = q4 >> 3, c4 = q4 & 7;
            int o = r * 36 + c4 * 4;
            Ad[o + 0] = f2tf(ra[i].x); Ad[o + 1] = f2tf(ra[i].y);
            Ad[o + 2] = f2tf(ra[i].z); Ad[o + 3] = f2tf(ra[i].w);
            Bd[o + 0] = f2tf(rb[i].x); Bd[o + 1] = f2tf(rb[i].y);
            Bd[o + 2] = f2tf(rb[i].z); Bd[o + 3] = f2tf(rb[i].w);
        }
    };

    float acc[2][8][4];
#pragma unroll
    for (int i = 0; i < 2; i++)
#pragma unroll
        for (int j = 0; j < 8; j++)
#pragma unroll
            for (int r = 0; r < 4; r++) acc[i][j][r] = 0.f;

    loadRegs(0); storeRegs(0); __syncthreads();

    for (int it = 0; it < 32; it++) {
        int cur = it & 1;
        if (it < 31) loadRegs((it + 1) * 32);
        const uint32_t* Ac = As + cur * (128 * 36);
        const uint32_t* Bc = Bs + cur * (128 * 36);
#pragma unroll
        for (int kk = 0; kk < 32; kk += 8) {
            uint32_t af[2][4], bf[8][2];
#pragma unroll
            for (int mi = 0; mi < 2; mi++) {
                int r = rowBase + mi * 16;
                af[mi][0] = Ac[(r + g) * 36 + kk + t];
                af[mi][1] = Ac[(r + g + 8) * 36 + kk + t];
                af[mi][2] = Ac[(r + g) * 36 + kk + t + 4];
                af[mi][3] = Ac[(r + g + 8) * 36 + kk + t + 4];
            }
#pragma unroll
            for (int ni = 0; ni < 8; ni++) {
                int c = colBase + ni * 8;
                bf[ni][0] = Bc[(c + g) * 36 + kk + t];
                bf[ni][1] = Bc[(c + g) * 36 + kk + t + 4];
            }
#pragma unroll
            for (int mi = 0; mi < 2; mi++)
#pragma unroll
                for (int ni = 0; ni < 8; ni++)
                    mma8(acc[mi][ni], af[mi], bf[ni]);
        }
        if (it < 31) storeRegs(cur ^ 1);
        __syncthreads();
    }

    // epilogue
#pragma unroll
    for (int mi = 0; mi < 2; mi++)
#pragma unroll
        for (int ni = 0; ni < 8; ni++)
#pragma unroll
            for (int h2 = 0; h2 < 2; h2++) {
                int row = m0 + rowBase + mi * 16 + g + h2 * 8;
                int col = n0 + colBase + ni * 8 + 2 * t;
                float v0 = acc[mi][ni][h2 * 2 + 0];
                float v1 = acc[mi][ni][h2 * 2 + 1];
                if (LAYOUT == 0) {
                    int b = row >> 11, s = row & (PS - 1);
                    int hh = col >> 6, d = col & 63;
                    size_t idx = ((size_t)(b * PH + hh) * PS + s) * PDH + d;
                    OUT[idx] = v0; OUT[idx + 1] = v1;
                } else if (LAYOUT == 1) {
                    int b = row >> 11, s = row & (PS - 1);
                    int hh = col >> 6, d = col & 63;
                    size_t idx = ((size_t)(b * PH + hh) * PDH + d) * PS + s;
                    OUT[idx] = v0; OUT[idx + PS] = v1;
                } else {
                    size_t idx = (size_t)row * PD + col;
                    OUT[idx]     = v0 + RES[idx];
                    OUT[idx + 1] = v1 + RES[idx + 1];
                }
            }
}

// ---------------- fused attention (256 thr, 8 warps 4x2, Q-frags in regs) ----
// Block = (bh, qt): 128 query rows of one head. S warp tile 32x64, O 32x32.
// Q fragments hoisted into registers once -> zero A-frag LDS in both QK passes.
__global__ __launch_bounds__(256)
void fused_attn_kernel(const float* __restrict__ QH, const float* __restrict__ KH,
                       const float* __restrict__ VT,
                       float* __restrict__ ATTN, float* __restrict__ OS)
{
    extern __shared__ uint32_t sm[];
    uint32_t* Qs = sm;                      // 128*68          = 8704
    uint32_t* Kb = sm + 8704;               // 2 * 128*68      = 17408
    uint32_t* Vb = sm + 26112;              // 64*132          = 8448
    uint32_t* Ps = sm + 34560;              // 128*132         = 16896
    float* sM   = (float*)(sm + 51456);     // 2*128
    float* sS   = sM + 256;                 // 2*128
    float* rowM = sS + 256;                 // 128
    float* rowI = rowM + 128;               // 128   (end: 52224 u32)

    const int tid = threadIdx.x;
    const int qt = blockIdx.x, bh = blockIdx.y;
    const int warpId = tid >> 5, lane = tid & 31;
    const int g = lane >> 2, t = lane & 3;
    const int wm = warpId >> 1, wn = warpId & 1;
    const int rowBase = wm * 32;

    const float* qbase = QH + ((size_t)bh * PS + qt * 128) * PDH;
    const float* kbase = KH + (size_t)bh * PS * PDH;
    const float* vbase = VT + (size_t)bh * PDH * PS;
    float* outbase = ATTN + ((size_t)bh * PS + qt * 128) * PS;

    // stage Q tile (tf32) once
#pragma unroll
    for (int i = 0; i < 8; i++) {
        int q4 = tid + i * 256, r = q4 >> 4, c4 = q4 & 15;
        float4 v = *(const float4*)(qbase + (size_t)r * PDH + c4 * 4);
        int o = r * 68 + c4 * 4;
        Qs[o + 0] = f2tf(v.x); Qs[o + 1] = f2tf(v.y);
        Qs[o + 2] = f2tf(v.z); Qs[o + 3] = f2tf(v.w);
    }
    __syncthreads();

    // hoist Q fragments to registers (used by BOTH QK passes)
    uint32_t qf[2][8][4];
#pragma unroll
    for (int mi = 0; mi < 2; mi++)
#pragma unroll
        for (int kx = 0; kx < 8; kx++) {
            int r = rowBase + mi * 16, kk = kx * 8;
            qf[mi][kx][0] = Qs[(r + g) * 68 + kk + t];
            qf[mi][kx][1] = Qs[(r + g + 8) * 68 + kk + t];
            qf[mi][kx][2] = Qs[(r + g) * 68 + kk + t + 4];
            qf[mi][kx][3] = Qs[(r + g + 8) * 68 + kk + t + 4];
        }

    float mrun[4], srun[4];
#pragma unroll
    for (int i = 0; i < 4; i++) { mrun[i] = -1e30f; srun[i] = 0.f; }

    float acc[2][8][4];

    // ---------------- pass 1: stats only ----------------
    {
        float4 kr[8];
        auto loadK = [&](int kt) {
            const float* kb = kbase + (size_t)kt * 128 * PDH;
#pragma unroll
            for (int i = 0; i < 8; i++) {
                int q4 = tid + i * 256, r = q4 >> 4, c4 = q4 & 15;
                kr[i] = *(const float4*)(kb + (size_t)r * PDH + c4 * 4);
            }
        };
        auto storeK = [&](int buf) {
            uint32_t* kd = Kb + buf * 8704;
#pragma unroll
            for (int i = 0; i < 8; i++) {
                int q4 = tid + i * 256, r = q4 >> 4, c4 = q4 & 15;
                int o = r * 68 + c4 * 4;
                kd[o + 0] = f2tf(kr[i].x); kd[o + 1] = f2tf(kr[i].y);
                kd[o + 2] = f2tf(kr[i].z); kd[o + 3] = f2tf(kr[i].w);
            }
        };

        loadK(0); storeK(0);
        __syncthreads();

        for (int kt = 0; kt < 16; kt++) {
            int cur = kt & 1;
            if (kt < 15) loadK(kt + 1);
            const uint32_t* kd = Kb + cur * 8704;
#pragma unroll
            for (int i = 0; i < 2; i++)
#pragma unroll
                for (int j = 0; j < 8; j++)
#pragma unroll
                    for (int r = 0; r < 4; r++) acc[i][j][r] = 0.f;
#pragma unroll
            for (int kx = 0; kx < 8; kx++) {
                int kk = kx * 8;
                uint32_t bf[8][2];
#pragma unroll
                for (int ni = 0; ni < 8; ni++) {
                    int c = wn * 64 + ni * 8;
                    bf[ni][0] = kd[(c + g) * 68 + kk + t];
                    bf[ni][1] = kd[(c + g) * 68 + kk + t + 4];
                }
#pragma unroll
                for (int mi = 0; mi < 2; mi++)
#pragma unroll
                    for (int ni = 0; ni < 8; ni++)
                        mma8(acc[mi][ni], qf[mi][kx], bf[ni]);
            }
            // online stats over this 128-col tile (per 64-col warp stripe)
#pragma unroll
            for (int mi = 0; mi < 2; mi++)
#pragma unroll
                for (int h2 = 0; h2 < 2; h2++) {
                    int idx = mi * 2 + h2;
                    float vmax = -1e30f;
#pragma unroll
                    for (int ni = 0; ni < 8; ni++) {
                        vmax = fmaxf(vmax, acc[mi][ni][h2 * 2 + 0]);
                        vmax = fmaxf(vmax, acc[mi][ni][h2 * 2 + 1]);
                    }
                    vmax = fmaxf(vmax, __shfl_xor_sync(0xffffffffu, vmax, 1));
                    vmax = fmaxf(vmax, __shfl_xor_sync(0xffffffffu, vmax, 2));
                    float mn = fmaxf(mrun[idx], vmax * 0.125f);
                    float ps = 0.f;
#pragma unroll
                    for (int ni = 0; ni < 8; ni++) {
                        ps += __expf(acc[mi][ni][h2 * 2 + 0] * 0.125f - mn);
                        ps += __expf(acc[mi][ni][h2 * 2 + 1] * 0.125f - mn);
                    }
                    ps += __shfl_xor_sync(0xffffffffu, ps, 1);
                    ps += __shfl_xor_sync(0xffffffffu, ps, 2);
                    srun[idx] = srun[idx] * __expf(mrun[idx] - mn) + ps;
                    mrun[idx] = mn;
                }
            if (kt < 15) storeK(cur ^ 1);
            __syncthreads();
        }
    }

    // merge the two 1024-col stripes per row
    if ((lane & 3) == 0) {
#pragma unroll
        for (int mi = 0; mi < 2; mi++)
#pragma unroll
            for (int h2 = 0; h2 < 2; h2++) {
                int row = rowBase + mi * 16 + h2 * 8 + g;
                sM[wn * 128 + row] = mrun[mi * 2 + h2];
                sS[wn * 128 + row] = srun[mi * 2 + h2];
            }
    }
    __syncthreads();
    if (tid < 128) {
        float m0 = sM[tid], m1 = sM[128 + tid];
        float m = fmaxf(m0, m1);
        float s = sS[tid] * __expf(m0 - m) + sS[128 + tid] * __expf(m1 - m);
        rowM[tid] = m; rowI[tid] = 1.0f / s;
    }
    __syncthreads();

    float rm[4], ri[4];
#pragma unroll
    for (int mi = 0; mi < 2; mi++)
#pragma unroll
        for (int h2 = 0; h2 < 2; h2++) {
            int row = rowBase + mi * 16 + h2 * 8 + g;
            rm[mi * 2 + h2] = rowM[row];
            ri[mi * 2 + h2] = rowI[row];
        }

    float oacc[2][4][4];
#pragma unroll
    for (int i = 0; i < 2; i++)
#pragma unroll
        for (int j = 0; j < 4; j++)
#pragma unroll
            for (int r = 0; r < 4; r++) oacc[i][j][r] = 0.f;

    const int colB2 = wn * 32;

    // ---------------- pass 2: recompute S -> p -> attn write + P@V ----------
    for (int kt = 0; kt < 16; kt++) {
        // load K tile (buffer 0) + V tile
        {
            const float* kb = kbase + (size_t)kt * 128 * PDH;
#pragma unroll
            for (int i = 0; i < 8; i++) {
                int q4 = tid + i * 256, r = q4 >> 4, c4 = q4 & 15;
                float4 v = *(const float4*)(kb + (size_t)r * PDH + c4 * 4);
                int o = r * 68 + c4 * 4;
                Kb[o + 0] = f2tf(v.x); Kb[o + 1] = f2tf(v.y);
                Kb[o + 2] = f2tf(v.z); Kb[o + 3] = f2tf(v.w);
            }
#pragma unroll
            for (int i = 0; i < 8; i++) {
                int q4 = tid + i * 256, d = q4 >> 5, c4 = q4 & 31;
                float4 v = *(const float4*)(vbase + (size_t)d * PS + kt * 128 + c4 * 4);
                int o = d * 132 + c4 * 4;
                Vb[o + 0] = f2tf(v.x); Vb[o + 1] = f2tf(v.y);
                Vb[o + 2] = f2tf(v.z); Vb[o + 3] = f2tf(v.w);
            }
        }
        __syncthreads();

        // recompute S (identical math to pass 1, Q frags from regs)
#pragma unroll
        for (int i = 0; i < 2; i++)
#pragma unroll
            for (int j = 0; j < 8; j++)
#pragma unroll
                for (int r = 0; r < 4; r++) acc[i][j][r] = 0.f;
#pragma unroll
        for (int kx = 0; kx < 8; kx++) {
            int kk = kx * 8;
            uint32_t bf[8][2];
#pragma unroll
            for (int ni = 0; ni < 8; ni++) {
                int c = wn * 64 + ni * 8;
                bf[ni][0] = Kb[(c + g) * 68 + kk + t];
                bf[ni][1] = Kb[(c + g) * 68 + kk + t + 4];
            }
#pragma unroll
            for (int mi = 0; mi < 2; mi++)
#pragma unroll
                for (int ni = 0; ni < 8; ni++)
                    mma8(acc[mi][ni], qf[mi][kx], bf[ni]);
        }

        // p = exp(s - m) * inv ; write attn; stage tf32 P
#pragma unroll
        for (int mi = 0; mi < 2; mi++)
#pragma unroll
            for (int ni = 0; ni < 8; ni++)
#pragma unroll
                for (int h2 = 0; h2 < 2; h2++) {
                    int idx = mi * 2 + h2;
                    int row = rowBase + mi * 16 + h2 * 8 + g;
                    int cl = wn * 64 + ni * 8 + 2 * t;
                    float p0 = __expf(acc[mi][ni][h2 * 2 + 0] * 0.125f - rm[idx]) * ri[idx];
                    float p1 = __expf(acc[mi][ni][h2 * 2 + 1] * 0.125f - rm[idx]) * ri[idx];
                    float2 st; st.x = p0; st.y = p1;
                    *(float2*)(outbase + (size_t)row * PS + kt * 128 + cl) = st;
                    Ps[row * 132 + cl]     = f2tf(p0);
                    Ps[row * 132 + cl + 1] = f2tf(p1);
                }
        __syncthreads();

        // P @ V  (warp tile 32x32 over O[128x64])
#pragma unroll
        for (int kk = 0; kk < 128; kk += 8) {
            uint32_t afv[2][4], bfv[4][2];
#pragma unroll
            for (int mi = 0; mi < 2; mi++) {
                int r = rowBase + mi * 16;
                afv[mi][0] = Ps[(r + g) * 132 + kk + t];
                afv[mi][1] = Ps[(r + g + 8) * 132 + kk + t];
                afv[mi][2] = Ps[(r + g) * 132 + kk + t + 4];
                afv[mi][3] = Ps[(r + g + 8) * 132 + kk + t + 4];
            }
#pragma unroll
            for (int ni = 0; ni < 4; ni++) {
                int c = colB2 + ni * 8;
                bfv[ni][0] = Vb[(c + g) * 132 + kk + t];
                bfv[ni][1] = Vb[(c + g) * 132 + kk + t + 4];
            }
#pragma unroll
            for (int mi = 0; mi < 2; mi++)
#pragma unroll
                for (int ni = 0; ni < 4; ni++)
                    mma8(oacc[mi][ni], afv[mi], bfv[ni]);
        }
        __syncthreads();
    }

    // O epilogue -> merged [B,S,D]
    int b = bh >> 4, hh = bh & 15;
#pragma unroll
    for (int mi = 0; mi < 2; mi++)
#pragma unroll
        for (int ni = 0; ni < 4; ni++)
#pragma unroll
            for (int h2 = 0; h2 < 2; h2++) {
                int row = rowBase + mi * 16 + h2 * 8 + g;
                int col = colB2 + ni * 8 + 2 * t;
                size_t idx = (size_t)(b * PS + qt * 128 + row) * PD + hh * 64 + col;
                float2 st;
                st.x = oacc[mi][ni][h2 * 2 + 0];
                st.y = oacc[mi][ni][h2 * 2 + 1];
                *(float2*)(OS + idx) = st;
            }
}

// ---------------- in-place LayerNorm over rows of d_out ----------------------
__global__ __launch_bounds__(256)
void ln_kernel(float* __restrict__ OUT, const float* __restrict__ LW,
               const float* __restrict__ LB)
{
    __shared__ float red[16];
    const int row = blockIdx.x, tid = threadIdx.x;
    float* rp = OUT + (size_t)row * PD;
    float4 v = *(const float4*)(rp + tid * 4);
    float s1 = v.x + v.y + v.z + v.w;
    float s2 = v.x * v.x + v.y * v.y + v.z * v.z + v.w * v.w;
#pragma unroll
    for (int o = 16; o; o >>= 1) {
        s1 += __shfl_xor_sync(0xffffffffu, s1, o);
        s2 += __shfl_xor_sync(0xffffffffu, s2, o);
    }
    int w = tid >> 5, l = tid & 31;
    if (l == 0) { red[w] = s1; red[w + 8] = s2; }
    __syncthreads();
    if (w == 0) {
        float a  = (l < 8) ? red[l] : 0.f;
        float b2 = (l < 8) ? red[l + 8] : 0.f;
#pragma unroll
        for (int o = 4; o; o >>= 1) {
            a  += __shfl_xor_sync(0xffffffffu, a, o);
            b2 += __shfl_xor_sync(0xffffffffu, b2, o);
        }
        if (l == 0) { red[0] = a; red[1] = b2; }
    }
    __syncthreads();
    float mean = red[0] * (1.0f / PD);
    float var  = red[1] * (1.0f / PD) - mean * mean;
    float inv  = rsqrtf(var + 1e-6f);
    float4 w4 = *(const float4*)(LW + tid * 4);
    float4 b4 = *(const float4*)(LB + tid * 4);
    float4 o4;
    o4.x = (v.x - mean) * inv * w4.x + b4.x;
    o4.y = (v.y - mean) * inv * w4.y + b4.y;
    o4.z = (v.z - mean) * inv * w4.z + b4.z;
    o4.w = (v.w - mean) * inv * w4.w + b4.w;
    *(float4*)(rp + tid * 4) = o4;
}

// ---------------- launcher ---------------------------------------------------
extern "C" void kernel_launch(void* const* d_in, const int* in_sizes, int n_in,
                              void* d_out, int out_size)
{
    const float* q   = (const float*)d_in[0];
    const float* k   = (const float*)d_in[1];
    const float* v   = (const float*)d_in[2];
    const float* wq  = (const float*)d_in[3];
    const float* wk  = (const float*)d_in[4];
    const float* wv  = (const float*)d_in[5];
    const float* wfc = (const float*)d_in[6];
    const float* lnw = (const float*)d_in[7];
    const float* lnb = (const float*)d_in[8];
    float* out  = (float*)d_out;
    float* attn = out + (size_t)O_ELEMS;   // outputs concatenated: o then attn

    float *qh, *kh, *vt, *os;
    cudaGetSymbolAddress((void**)&qh, g_qh);
    cudaGetSymbolAddress((void**)&kh, g_kh);
    cudaGetSymbolAddress((void**)&vt, g_vt);
    cudaGetSymbolAddress((void**)&os, g_os);

    const int proj_smem  = 4 * 128 * 36 * 4;    // 73728 B
    const int fused_smem = 52224 * 4;           // 208896 B
    cudaFuncSetAttribute(proj_kernel<0>,
                         cudaFuncAttributeMaxDynamicSharedMemorySize, proj_smem);
    cudaFuncSetAttribute(proj_kernel<1>,
                         cudaFuncAttributeMaxDynamicSharedMemorySize, proj_smem);
    cudaFuncSetAttribute(proj_kernel<2>,
                         cudaFuncAttributeMaxDynamicSharedMemorySize, proj_smem);
    cudaFuncSetAttribute(fused_attn_kernel,
                         cudaFuncAttributeMaxDynamicSharedMemorySize, fused_smem);

    proj_kernel<0><<<dim3(8, 64), 256, proj_smem>>>(q, wq, nullptr, qh);
    proj_kernel<0><<<dim3(8, 64), 256, proj_smem>>>(k, wk, nullptr, kh);
    proj_kernel<1><<<dim3(8, 64), 256, proj_smem>>>(v, wv, nullptr, vt);
    fused_attn_kernel<<<dim3(16, 64), 256, fused_smem>>>(qh, kh, vt, attn, os);
    proj_kernel<2><<<dim3(8, 64), 256, proj_smem>>>(os, wfc, q, out);
    ln_kernel<<<MROWS, 256>>>(out, lnw, lnb);
}

// round 11
// speedup vs baseline: 1.7456x; 1.6455x over previous
#include <cuda_runtime.h>
#include <cuda_fp16.h>
#include <cstdint>

// Problem constants
#define PB  4
#define PS  2048
#define PD  1024
#define PH  16
#define PDH 64
#define MROWS (PB*PS)        // 8192
#define O_ELEMS (MROWS*PD)   // 8388608  (offset of attn in d_out)

// ---------------- device scratch (static: no allocations allowed) -------------
__device__ __half g_qh[(size_t)PB*PH*PS*PDH]; // [B,H,S,dh]   fp16
__device__ __half g_kh[(size_t)PB*PH*PS*PDH]; // [B,H,S,dh]   fp16
__device__ __half g_vt[(size_t)PB*PH*PDH*PS]; // [B,H,dh,S]   fp16 (transposed V)
__device__ float  g_os[(size_t)PB*PS*PD];     // merged attention output [B,S,D]

// ---------------- helpers -----------------------------------------------------
__device__ __forceinline__ void mma16(float* d, const uint32_t* a, const uint32_t* b) {
    asm volatile(
        "mma.sync.aligned.m16n8k16.row.col.f32.f16.f16.f32 "
        "{%0,%1,%2,%3},{%4,%5,%6,%7},{%8,%9},{%0,%1,%2,%3};"
        : "+f"(d[0]), "+f"(d[1]), "+f"(d[2]), "+f"(d[3])
        : "r"(a[0]), "r"(a[1]), "r"(a[2]), "r"(a[3]), "r"(b[0]), "r"(b[1]));
}
__device__ __forceinline__ uint32_t h2bits(__half2 h) {
    uint32_t u; __builtin_memcpy(&u, &h, 4); return u;
}
__device__ __forceinline__ void cpa16(uint32_t dst, const void* src) {
    asm volatile("cp.async.ca.shared.global [%0], [%1], 16;" :: "r"(dst), "l"(src));
}
__device__ __forceinline__ void cpa_commit() { asm volatile("cp.async.commit_group;"); }
template<int N> __device__ __forceinline__ void cpa_wait() {
    asm volatile("cp.async.wait_group %0;" :: "n"(N));
}
__device__ __forceinline__ uint32_t smem_u32(const void* p) {
    uint32_t a;
    asm("{ .reg .u64 t; cvta.to.shared.u64 t, %1; cvt.u32.u64 %0, t; }" : "=r"(a) : "l"(p));
    return a;
}

// ---------------- projection GEMM (fp16 MMA, double-buffered) ----------------
// C[M,N] = X[M,K] @ W[N,K]^T. BM=128, BN=128, BK=32, 256 thr, warps 4x2 (32x64).
// Staged as half2, row stride 20 half2 (conflict-free: 4g+t pattern).
// LAYOUT 0: scatter half [B,H,S,dh] | 1: scatter half [B,H,dh,S] | 2: f32 + residual
template<int LAYOUT>
__global__ __launch_bounds__(256)
void proj_kernel(const float* __restrict__ X, const float* __restrict__ W,
                 const float* __restrict__ RES, void* __restrict__ OUTv)
{
    extern __shared__ uint32_t psm[];
    uint32_t* As = psm;                 // 2 buffers of 128*20
    uint32_t* Bs = psm + 2 * 128 * 20;  // 2 buffers of 128*20
    const int tid = threadIdx.x;
    const int m0 = blockIdx.y * 128;
    const int n0 = blockIdx.x * 128;
    const int warpId = tid >> 5, lane = tid & 31;
    const int g = lane >> 2, t = lane & 3;
    const int wm = warpId >> 1, wn = warpId & 1;
    const int rowBase = wm * 32, colBase = wn * 64;

    float4 ra[4], rb[4];
    auto loadRegs = [&](int kt) {
#pragma unroll
        for (int i = 0; i < 4; i++) {
            int q4 = tid + i * 256, r = q4 >> 3, c4 = q4 & 7;
            ra[i] = *(const float4*)(X + (size_t)(m0 + r) * PD + kt + c4 * 4);
            rb[i] = *(const float4*)(W + (size_t)(n0 + r) * PD + kt + c4 * 4);
        }
    };
    auto storeRegs = [&](int buf) {
        uint32_t* Ad = As + buf * (128 * 20);
        uint32_t* Bd = Bs + buf * (128 * 20);
#pragma unroll
        for (int i = 0; i < 4; i++) {
            int q4 = tid + i * 256, r = q4 >> 3, c4 = q4 & 7;
            int o = r * 20 + c4 * 2;
            *(uint2*)(Ad + o) = make_uint2(
                h2bits(__floats2half2_rn(ra[i].x, ra[i].y)),
                h2bits(__floats2half2_rn(ra[i].z, ra[i].w)));
            *(uint2*)(Bd + o) = make_uint2(
                h2bits(__floats2half2_rn(rb[i].x, rb[i].y)),
                h2bits(__floats2half2_rn(rb[i].z, rb[i].w)));
        }
    };

    float acc[2][8][4];
#pragma unroll
    for (int i = 0; i < 2; i++)
#pragma unroll
        for (int j = 0; j < 8; j++)
#pragma unroll
            for (int r = 0; r < 4; r++) acc[i][j][r] = 0.f;

    loadRegs(0); storeRegs(0); __syncthreads();

    for (int it = 0; it < 32; it++) {
        int cur = it & 1;
        if (it < 31) loadRegs((it + 1) * 32);
        const uint32_t* Ac = As + cur * (128 * 20);
        const uint32_t* Bc = Bs + cur * (128 * 20);
#pragma unroll
        for (int kx = 0; kx < 2; kx++) {          // two k16 steps per BK=32
            uint32_t af[2][4], bf[8][2];
#pragma unroll
            for (int mi = 0; mi < 2; mi++) {
                int r = rowBase + mi * 16;
                af[mi][0] = Ac[(r + g) * 20 + kx * 8 + t];
                af[mi][1] = Ac[(r + g + 8) * 20 + kx * 8 + t];
                af[mi][2] = Ac[(r + g) * 20 + kx * 8 + t + 4];
                af[mi][3] = Ac[(r + g + 8) * 20 + kx * 8 + t + 4];
            }
#pragma unroll
            for (int ni = 0; ni < 8; ni++) {
                int c = colBase + ni * 8;
                bf[ni][0] = Bc[(c + g) * 20 + kx * 8 + t];
                bf[ni][1] = Bc[(c + g) * 20 + kx * 8 + t + 4];
            }
#pragma unroll
            for (int mi = 0; mi < 2; mi++)
#pragma unroll
                for (int ni = 0; ni < 8; ni++)
                    mma16(acc[mi][ni], af[mi], bf[ni]);
        }
        if (it < 31) storeRegs(cur ^ 1);
        __syncthreads();
    }

    // epilogue
#pragma unroll
    for (int mi = 0; mi < 2; mi++)
#pragma unroll
        for (int ni = 0; ni < 8; ni++)
#pragma unroll
            for (int h2 = 0; h2 < 2; h2++) {
                int row = m0 + rowBase + mi * 16 + g + h2 * 8;
                int col = n0 + colBase + ni * 8 + 2 * t;
                float v0 = acc[mi][ni][h2 * 2 + 0];
                float v1 = acc[mi][ni][h2 * 2 + 1];
                if (LAYOUT == 0) {
                    __half* OUT = (__half*)OUTv;
                    int b = row >> 11, s = row & (PS - 1);
                    int hh = col >> 6, d = col & 63;
                    size_t idx = ((size_t)(b * PH + hh) * PS + s) * PDH + d;
                    *(__half2*)(OUT + idx) = __floats2half2_rn(v0, v1);
                } else if (LAYOUT == 1) {
                    __half* OUT = (__half*)OUTv;
                    int b = row >> 11, s = row & (PS - 1);
                    int hh = col >> 6, d = col & 63;
                    size_t idx = ((size_t)(b * PH + hh) * PDH + d) * PS + s;
                    OUT[idx]      = __float2half(v0);
                    OUT[idx + PS] = __float2half(v1);
                } else {
                    float* OUT = (float*)OUTv;
                    size_t idx = (size_t)row * PD + col;
                    OUT[idx]     = v0 + RES[idx];
                    OUT[idx + 1] = v1 + RES[idx + 1];
                }
            }
}

// ---------------- fused attention (512 thr, 16 warps 4x4, fp16 MMA) ----------
// Block = (bh, qt): 128 query rows of one head. S warp tile 32x32, O 32x16.
// All tiles land in smem via cp.async (data already fp16 in gmem).
// Pass 1: stream K (double-buffered), online per-row stats (4 stripes/row).
// Pass 2: re-stream K+V (L2-hot, double-buffered), recompute S bitwise-identically,
//         p=exp(s-m)*inv, write attn (f32), stage half2 P, accumulate P@V.
// smem layout (u32 units): Qs 128x36 | Kb 2x128x36 | Vb 2x64x68 | Ps 128x68 | stats
#define QS_OFF 0
#define KB_OFF 4608
#define VB_OFF 13824
#define PS_OFF 22528
#define ST_OFF 31232
#define FUSED_SMEM_U32 32512

__global__ __launch_bounds__(512, 1)
void fused_attn_kernel(const __half* __restrict__ QH, const __half* __restrict__ KH,
                       const __half* __restrict__ VT,
                       float* __restrict__ ATTN, float* __restrict__ OS)
{
    extern __shared__ uint32_t sm[];
    float* sM   = (float*)(sm + ST_OFF);     // 4*128
    float* sS   = sM + 512;                  // 4*128
    float* rowM = sS + 512;                  // 128
    float* rowI = rowM + 128;                // 128

    const int tid = threadIdx.x;
    const int qt = blockIdx.x, bh = blockIdx.y;
    const int warpId = tid >> 5, lane = tid & 31;
    const int g = lane >> 2, t = lane & 3;
    const int wm = warpId >> 2, wn = warpId & 3;   // 4x4 warp grid
    const int rowBase = wm * 32;
    const int colS = wn * 32;                      // S-col stripe
    const int colO = wn * 16;                      // O-col stripe

    const __half* qbase = QH + ((size_t)bh * PS + qt * 128) * PDH;
    const __half* kbase = KH + (size_t)bh * PS * PDH;
    const __half* vbase = VT + (size_t)bh * PDH * PS;
    float* outbase = ATTN + ((size_t)bh * PS + qt * 128) * PS;

    const uint32_t sbase = smem_u32(sm);

    auto issueQ = [&]() {
#pragma unroll
        for (int i = 0; i < 2; i++) {
            int q = tid + i * 512, r = q >> 3, c16 = q & 7;
            cpa16(sbase + (QS_OFF + r * 36 + c16 * 4) * 4, qbase + r * 64 + c16 * 8);
        }
    };
    auto issueK = [&](int kt, int buf) {
        const __half* kb = kbase + (size_t)kt * 128 * PDH;
#pragma unroll
        for (int i = 0; i < 2; i++) {
            int q = tid + i * 512, r = q >> 3, c16 = q & 7;
            cpa16(sbase + (KB_OFF + buf * 4608 + r * 36 + c16 * 4) * 4,
                  kb + r * 64 + c16 * 8);
        }
    };
    auto issueV = [&](int kt, int buf) {
#pragma unroll
        for (int i = 0; i < 2; i++) {
            int q = tid + i * 512, d = q >> 4, c16 = q & 15;
            cpa16(sbase + (VB_OFF + buf * 4352 + d * 68 + c16 * 4) * 4,
                  vbase + (size_t)d * PS + kt * 128 + c16 * 8);
        }
    };

    // Q (group) then K0 (group)
    issueQ();       cpa_commit();
    issueK(0, 0);   cpa_commit();
    cpa_wait<1>();  // Q complete (K0 may still be in flight)
    __syncthreads();

    // hoist Q fragments (used by BOTH QK passes -> bitwise identical S)
    uint32_t qf[2][4][4];
#pragma unroll
    for (int mi = 0; mi < 2; mi++)
#pragma unroll
        for (int kx = 0; kx < 4; kx++) {
            int r = rowBase + mi * 16;
            qf[mi][kx][0] = sm[QS_OFF + (r + g) * 36 + kx * 8 + t];
            qf[mi][kx][1] = sm[QS_OFF + (r + g + 8) * 36 + kx * 8 + t];
            qf[mi][kx][2] = sm[QS_OFF + (r + g) * 36 + kx * 8 + t + 4];
            qf[mi][kx][3] = sm[QS_OFF + (r + g + 8) * 36 + kx * 8 + t + 4];
        }

    float mrun[4], srun[4];
#pragma unroll
    for (int i = 0; i < 4; i++) { mrun[i] = -1e30f; srun[i] = 0.f; }

    float acc[2][4][4];

    // ---------------- pass 1: stats only ----------------
    for (int kt = 0; kt < 16; kt++) {
        int cur = kt & 1;
        if (kt < 15) { issueK(kt + 1, cur ^ 1); cpa_commit(); }
        if (kt < 15) cpa_wait<1>(); else cpa_wait<0>();
        __syncthreads();
        const uint32_t* kd = sm + KB_OFF + cur * 4608;
#pragma unroll
        for (int i = 0; i < 2; i++)
#pragma unroll
            for (int j = 0; j < 4; j++)
#pragma unroll
                for (int r = 0; r < 4; r++) acc[i][j][r] = 0.f;
#pragma unroll
        for (int kx = 0; kx < 4; kx++) {
            uint32_t bf[4][2];
#pragma unroll
            for (int ni = 0; ni < 4; ni++) {
                int c = colS + ni * 8;
                bf[ni][0] = kd[(c + g) * 36 + kx * 8 + t];
                bf[ni][1] = kd[(c + g) * 36 + kx * 8 + t + 4];
            }
#pragma unroll
            for (int mi = 0; mi < 2; mi++)
#pragma unroll
                for (int ni = 0; ni < 4; ni++)
                    mma16(acc[mi][ni], qf[mi][kx], bf[ni]);
        }
        // online stats over this tile (per 32-col warp stripe)
#pragma unroll
        for (int mi = 0; mi < 2; mi++)
#pragma unroll
            for (int h2 = 0; h2 < 2; h2++) {
                int idx = mi * 2 + h2;
                float vmax = -1e30f;
#pragma unroll
                for (int ni = 0; ni < 4; ni++) {
                    vmax = fmaxf(vmax, acc[mi][ni][h2 * 2 + 0]);
                    vmax = fmaxf(vmax, acc[mi][ni][h2 * 2 + 1]);
                }
                vmax = fmaxf(vmax, __shfl_xor_sync(0xffffffffu, vmax, 1));
                vmax = fmaxf(vmax, __shfl_xor_sync(0xffffffffu, vmax, 2));
                float mn = fmaxf(mrun[idx], vmax * 0.125f);
                float ps = 0.f;
#pragma unroll
                for (int ni = 0; ni < 4; ni++) {
                    ps += __expf(acc[mi][ni][h2 * 2 + 0] * 0.125f - mn);
                    ps += __expf(acc[mi][ni][h2 * 2 + 1] * 0.125f - mn);
                }
                ps += __shfl_xor_sync(0xffffffffu, ps, 1);
                ps += __shfl_xor_sync(0xffffffffu, ps, 2);
                srun[idx] = srun[idx] * __expf(mrun[idx] - mn) + ps;
                mrun[idx] = mn;
            }
        __syncthreads();
    }

    // merge the four 32-col stripes per row
    if ((lane & 3) == 0) {
#pragma unroll
        for (int mi = 0; mi < 2; mi++)
#pragma unroll
            for (int h2 = 0; h2 < 2; h2++) {
                int row = rowBase + mi * 16 + h2 * 8 + g;
                sM[wn * 128 + row] = mrun[mi * 2 + h2];
                sS[wn * 128 + row] = srun[mi * 2 + h2];
            }
    }
    __syncthreads();
    if (tid < 128) {
        float m0 = sM[tid],       m1 = sM[128 + tid];
        float m2 = sM[256 + tid], m3 = sM[384 + tid];
        float m = fmaxf(fmaxf(m0, m1), fmaxf(m2, m3));
        float s = sS[tid] * __expf(m0 - m) + sS[128 + tid] * __expf(m1 - m)
                + sS[256 + tid] * __expf(m2 - m) + sS[384 + tid] * __expf(m3 - m);
        rowM[tid] = m; rowI[tid] = 1.0f / s;
    }
    __syncthreads();

    float rm[4], ri[4];
#pragma unroll
    for (int mi = 0; mi < 2; mi++)
#pragma unroll
        for (int h2 = 0; h2 < 2; h2++) {
            int row = rowBase + mi * 16 + h2 * 8 + g;
            rm[mi * 2 + h2] = rowM[row];
            ri[mi * 2 + h2] = rowI[row];
        }

    float oacc[2][2][4];
#pragma unroll
    for (int i = 0; i < 2; i++)
#pragma unroll
        for (int j = 0; j < 2; j++)
#pragma unroll
            for (int r = 0; r < 4; r++) oacc[i][j][r] = 0.f;

    // ---------------- pass 2: recompute S -> p -> attn write + P@V ----------
    issueK(0, 0); issueV(0, 0); cpa_commit();
    for (int kt = 0; kt < 16; kt++) {
        int cur = kt & 1;
        if (kt < 15) { issueK(kt + 1, cur ^ 1); issueV(kt + 1, cur ^ 1); cpa_commit(); }
        if (kt < 15) cpa_wait<1>(); else cpa_wait<0>();
        __syncthreads();
        const uint32_t* kd = sm + KB_OFF + cur * 4608;
        const uint32_t* vd = sm + VB_OFF + cur * 4352;

        // recompute S (identical math/order to pass 1)
#pragma unroll
        for (int i = 0; i < 2; i++)
#pragma unroll
            for (int j = 0; j < 4; j++)
#pragma unroll
                for (int r = 0; r < 4; r++) acc[i][j][r] = 0.f;
#pragma unroll
        for (int kx = 0; kx < 4; kx++) {
            uint32_t bf[4][2];
#pragma unroll
            for (int ni = 0; ni < 4; ni++) {
                int c = colS + ni * 8;
                bf[ni][0] = kd[(c + g) * 36 + kx * 8 + t];
                bf[ni][1] = kd[(c + g) * 36 + kx * 8 + t + 4];
            }
#pragma unroll
            for (int mi = 0; mi < 2; mi++)
#pragma unroll
                for (int ni = 0; ni < 4; ni++)
                    mma16(acc[mi][ni], qf[mi][kx], bf[ni]);
        }

        // p = exp(s - m) * inv ; write attn (f32) ; stage half2 P
#pragma unroll
        for (int mi = 0; mi < 2; mi++)
#pragma unroll
            for (int ni = 0; ni < 4; ni++)
#pragma unroll
                for (int h2 = 0; h2 < 2; h2++) {
                    int idx = mi * 2 + h2;
                    int row = rowBase + mi * 16 + h2 * 8 + g;
                    int cl = colS + ni * 8 + 2 * t;
                    float p0 = __expf(acc[mi][ni][h2 * 2 + 0] * 0.125f - rm[idx]) * ri[idx];
                    float p1 = __expf(acc[mi][ni][h2 * 2 + 1] * 0.125f - rm[idx]) * ri[idx];
                    float2 st; st.x = p0; st.y = p1;
                    *(float2*)(outbase + (size_t)row * PS + kt * 128 + cl) = st;
                    sm[PS_OFF + row * 68 + (cl >> 1)] = h2bits(__floats2half2_rn(p0, p1));
                }
        __syncthreads();

        // P @ V  (warp tile 32x16 over O[128x64], 8 k16 steps)
#pragma unroll
        for (int kx = 0; kx < 8; kx++) {
            uint32_t afv[2][4], bfv[2][2];
#pragma unroll
            for (int mi = 0; mi < 2; mi++) {
                int r = rowBase + mi * 16;
                afv[mi][0] = sm[PS_OFF + (r + g) * 68 + kx * 8 + t];
                afv[mi][1] = sm[PS_OFF + (r + g + 8) * 68 + kx * 8 + t];
                afv[mi][2] = sm[PS_OFF + (r + g) * 68 + kx * 8 + t + 4];
                afv[mi][3] = sm[PS_OFF + (r + g + 8) * 68 + kx * 8 + t + 4];
            }
#pragma unroll
            for (int ni = 0; ni < 2; ni++) {
                int c = colO + ni * 8;
                bfv[ni][0] = vd[(c + g) * 68 + kx * 8 + t];
                bfv[ni][1] = vd[(c + g) * 68 + kx * 8 + t + 4];
            }
#pragma unroll
            for (int mi = 0; mi < 2; mi++)
#pragma unroll
                for (int ni = 0; ni < 2; ni++)
                    mma16(oacc[mi][ni], afv[mi], bfv[ni]);
        }
        __syncthreads();
    }

    // O epilogue -> merged [B,S,D]
    int b = bh >> 4, hh = bh & 15;
#pragma unroll
    for (int mi = 0; mi < 2; mi++)
#pragma unroll
        for (int ni = 0; ni < 2; ni++)
#pragma unroll
            for (int h2 = 0; h2 < 2; h2++) {
                int row = rowBase + mi * 16 + h2 * 8 + g;
                int col = colO + ni * 8 + 2 * t;
                size_t idx = (size_t)(b * PS + qt * 128 + row) * PD + hh * 64 + col;
                float2 st;
                st.x = oacc[mi][ni][h2 * 2 + 0];
                st.y = oacc[mi][ni][h2 * 2 + 1];
                *(float2*)(OS + idx) = st;
            }
}

// ---------------- in-place LayerNorm over rows of d_out ----------------------
__global__ __launch_bounds__(256)
void ln_kernel(float* __restrict__ OUT, const float* __restrict__ LW,
               const float* __restrict__ LB)
{
    __shared__ float red[16];
    const int row = blockIdx.x, tid = threadIdx.x;
    float* rp = OUT + (size_t)row * PD;
    float4 v = *(const float4*)(rp + tid * 4);
    float s1 = v.x + v.y + v.z + v.w;
    float s2 = v.x * v.x + v.y * v.y + v.z * v.z + v.w * v.w;
#pragma unroll
    for (int o = 16; o; o >>= 1) {
        s1 += __shfl_xor_sync(0xffffffffu, s1, o);
        s2 += __shfl_xor_sync(0xffffffffu, s2, o);
    }
    int w = tid >> 5, l = tid & 31;
    if (l == 0) { red[w] = s1; red[w + 8] = s2; }
    __syncthreads();
    if (w == 0) {
        float a  = (l < 8) ? red[l] : 0.f;
        float b2 = (l < 8) ? red[l + 8] : 0.f;
#pragma unroll
        for (int o = 4; o; o >>= 1) {
            a  += __shfl_xor_sync(0xffffffffu, a, o);
            b2 += __shfl_xor_sync(0xffffffffu, b2, o);
        }
        if (l == 0) { red[0] = a; red[1] = b2; }
    }
    __syncthreads();
    float mean = red[0] * (1.0f / PD);
    float var  = red[1] * (1.0f / PD) - mean * mean;
    float inv  = rsqrtf(var + 1e-6f);
    float4 w4 = *(const float4*)(LW + tid * 4);
    float4 b4 = *(const float4*)(LB + tid * 4);
    float4 o4;
    o4.x = (v.x - mean) * inv * w4.x + b4.x;
    o4.y = (v.y - mean) * inv * w4.y + b4.y;
    o4.z = (v.z - mean) * inv * w4.z + b4.z;
    o4.w = (v.w - mean) * inv * w4.w + b4.w;
    *(float4*)(rp + tid * 4) = o4;
}

// ---------------- launcher ---------------------------------------------------
extern "C" void kernel_launch(void* const* d_in, const int* in_sizes, int n_in,
                              void* d_out, int out_size)
{
    const float* q   = (const float*)d_in[0];
    const float* k   = (const float*)d_in[1];
    const float* v   = (const float*)d_in[2];
    const float* wq  = (const float*)d_in[3];
    const float* wk  = (const float*)d_in[4];
    const float* wv  = (const float*)d_in[5];
    const float* wfc = (const float*)d_in[6];
    const float* lnw = (const float*)d_in[7];
    const float* lnb = (const float*)d_in[8];
    float* out  = (float*)d_out;
    float* attn = out + (size_t)O_ELEMS;   // outputs concatenated: o then attn

    __half *qh, *kh, *vt; float *os;
    cudaGetSymbolAddress((void**)&qh, g_qh);
    cudaGetSymbolAddress((void**)&kh, g_kh);
    cudaGetSymbolAddress((void**)&vt, g_vt);
    cudaGetSymbolAddress((void**)&os, g_os);

    const int proj_smem  = 4 * 128 * 20 * 4;        // 40960 B
    const int fused_smem = FUSED_SMEM_U32 * 4;      // 130048 B
    cudaFuncSetAttribute(proj_kernel<0>,
                         cudaFuncAttributeMaxDynamicSharedMemorySize, proj_smem);
    cudaFuncSetAttribute(proj_kernel<1>,
                         cudaFuncAttributeMaxDynamicSharedMemorySize, proj_smem);
    cudaFuncSetAttribute(proj_kernel<2>,
                         cudaFuncAttributeMaxDynamicSharedMemorySize, proj_smem);
    cudaFuncSetAttribute(fused_attn_kernel,
                         cudaFuncAttributeMaxDynamicSharedMemorySize, fused_smem);

    proj_kernel<0><<<dim3(8, 64), 256, proj_smem>>>(q, wq, nullptr, qh);
    proj_kernel<0><<<dim3(8, 64), 256, proj_smem>>>(k, wk, nullptr, kh);
    proj_kernel<1><<<dim3(8, 64), 256, proj_smem>>>(v, wv, nullptr, vt);
    fused_attn_kernel<<<dim3(16, 64), 512, fused_smem>>>(qh, kh, vt, attn, os);
    proj_kernel<2><<<dim3(8, 64), 256, proj_smem>>>(os, wfc, q, out);
    ln_kernel<<<MROWS, 256>>>(out, lnw, lnb);
}